// round 1
// baseline (speedup 1.0000x reference)
#include <cuda_runtime.h>
#include <math.h>

#define NL 4
#define H  1024
#define E  2048
#define G3 3072
#define OUTN 50257

// Scratch (no device allocation allowed) — persistent __device__ globals.
__device__ float g_x[E];          // current layer input vector (E = 2H)
__device__ float g_gi[2 * G3];    // W_ih @ x + b_ih  for both directions
__device__ float g_gh[2 * G3];    // W_hh @ h + b_hh  for both directions

// ---------------------------------------------------------------------------
// Embedding lookup: x = embed_table[features[0]]
// ---------------------------------------------------------------------------
__global__ void embed_kernel(const int* __restrict__ feat,
                             const float* __restrict__ table) {
    int i = blockIdx.x * blockDim.x + threadIdx.x;
    if (i < E) {
        g_x[i] = table[(size_t)feat[0] * E + i];
    }
}

// ---------------------------------------------------------------------------
// Per-layer gate GEMVs: for each of 2*3H rows,
//   gi[row] = w_ih[l,d,j,:] . x  + b_ih[l,d,j]
//   gh[row] = w_hh[l,d,j,:] . h  + b_hh[l,d,j]
// One 256-thread block per row; coalesced float4 loads; warp+shared reduce.
// ---------------------------------------------------------------------------
__global__ void __launch_bounds__(256) gates_kernel(
    const float* __restrict__ wih, const float* __restrict__ whh,
    const float* __restrict__ bih, const float* __restrict__ bhh,
    const float* __restrict__ hidden, int l) {

    int row = blockIdx.x;            // 0 .. 6143
    int d = (row >= G3) ? 1 : 0;
    int j = row - d * G3;

    const float4* wi = (const float4*)(wih + ((size_t)(l * 2 + d) * G3 + j) * E);
    const float4* wh = (const float4*)(whh + ((size_t)(l * 2 + d) * G3 + j) * H);
    const float4* xv = (const float4*)g_x;
    const float4* hv = (const float4*)(hidden + (size_t)(2 * l + d) * H);

    int t = threadIdx.x;
    float si = 0.f, sh = 0.f;

    // E/4 = 512 float4 over 256 threads -> 2 per thread
    #pragma unroll
    for (int k = 0; k < 2; k++) {
        float4 w = wi[t + k * 256];
        float4 x = xv[t + k * 256];
        si += w.x * x.x + w.y * x.y + w.z * x.z + w.w * x.w;
    }
    // H/4 = 256 float4 over 256 threads -> 1 per thread
    {
        float4 w = wh[t];
        float4 h = hv[t];
        sh += w.x * h.x + w.y * h.y + w.z * h.z + w.w * h.w;
    }

    // warp reduce both sums
    #pragma unroll
    for (int o = 16; o; o >>= 1) {
        si += __shfl_xor_sync(0xffffffffu, si, o);
        sh += __shfl_xor_sync(0xffffffffu, sh, o);
    }

    __shared__ float ri[8], rh[8];
    int warp = t >> 5, lane = t & 31;
    if (lane == 0) { ri[warp] = si; rh[warp] = sh; }
    __syncthreads();

    if (t == 0) {
        float ti = 0.f, th = 0.f;
        #pragma unroll
        for (int w = 0; w < 8; w++) { ti += ri[w]; th += rh[w]; }
        size_t boff = (size_t)(l * 2 + d) * G3 + j;
        g_gi[row] = ti + bih[boff];
        g_gh[row] = th + bhh[boff];
    }
}

// ---------------------------------------------------------------------------
// Combine: GRU nonlinearity per (d, j). Writes new hidden to d_out and to g_x
// (concat(fwd,bwd) = next layer's input, 2H == E).
// ---------------------------------------------------------------------------
__device__ __forceinline__ float sigmoidf(float x) {
    return 1.0f / (1.0f + expf(-x));
}

__global__ void __launch_bounds__(1024) combine_kernel(
    const float* __restrict__ hidden, float* __restrict__ out, int l) {

    int idx = blockIdx.x * 1024 + threadIdx.x;   // 0 .. 2047
    int d = (idx >= H) ? 1 : 0;
    int j = idx - d * H;

    int base = d * G3;
    float ir = g_gi[base + j],         hr = g_gh[base + j];
    float iz = g_gi[base + H + j],     hz = g_gh[base + H + j];
    float in_ = g_gi[base + 2 * H + j], hn = g_gh[base + 2 * H + j];

    float r = sigmoidf(ir + hr);
    float z = sigmoidf(iz + hz);
    float n = tanhf(in_ + r * hn);
    float hold = hidden[(size_t)(2 * l + d) * H + j];
    float hnew = (1.0f - z) * n + z * hold;

    g_x[idx] = hnew;                                  // next layer input
    out[OUTN + (size_t)(2 * l + d) * H + j] = hnew;   // new_hidden output
}

// ---------------------------------------------------------------------------
// FC: logits[r] = fc_w[r,:] . x + fc_b[r].  Warp-per-row, 4 rows per block,
// x staged in shared once per block. 16 independent float4 loads per lane.
// ---------------------------------------------------------------------------
__global__ void __launch_bounds__(128) fc_kernel(
    const float* __restrict__ fcw, const float* __restrict__ fcb,
    float* __restrict__ out) {

    __shared__ __align__(16) float sx[E];
    int tid = threadIdx.x;
    for (int i = tid; i < E; i += 128) sx[i] = g_x[i];
    __syncthreads();

    int warp = tid >> 5, lane = tid & 31;
    int r = blockIdx.x * 4 + warp;
    if (r >= OUTN) return;

    const float4* wr = (const float4*)(fcw + (size_t)r * E);
    const float4* xv = (const float4*)sx;

    float sum = 0.f;
    #pragma unroll
    for (int k = 0; k < 16; k++) {
        float4 w = wr[lane + k * 32];
        float4 x = xv[lane + k * 32];
        sum += w.x * x.x + w.y * x.y + w.z * x.z + w.w * x.w;
    }
    #pragma unroll
    for (int o = 16; o; o >>= 1) sum += __shfl_xor_sync(0xffffffffu, sum, o);

    if (lane == 0) out[r] = sum + fcb[r];
}

// ---------------------------------------------------------------------------
// Launch: embed -> 4 x (gates, combine) -> fc.   All default-stream,
// graph-capturable, no allocation, no sync.
// Input order (metadata): features(i32,1), hidden(8192), embed_table,
// w_ih, w_hh, b_ih, b_hh, fc_w, fc_b.
// Output: logits[0,50257) then new_hidden[50257,58449).
// ---------------------------------------------------------------------------
extern "C" void kernel_launch(void* const* d_in, const int* in_sizes, int n_in,
                              void* d_out, int out_size) {
    const int*   feat   = (const int*)  d_in[0];
    const float* hidden = (const float*)d_in[1];
    const float* table  = (const float*)d_in[2];
    const float* wih    = (const float*)d_in[3];
    const float* whh    = (const float*)d_in[4];
    const float* bih    = (const float*)d_in[5];
    const float* bhh    = (const float*)d_in[6];
    const float* fcw    = (const float*)d_in[7];
    const float* fcb    = (const float*)d_in[8];
    float* out = (float*)d_out;

    embed_kernel<<<(E + 255) / 256, 256>>>(feat, table);

    for (int l = 0; l < NL; l++) {
        gates_kernel<<<2 * G3, 256>>>(wih, whh, bih, bhh, hidden, l);
        combine_kernel<<<2, 1024>>>(hidden, out, l);
    }

    fc_kernel<<<(OUTN + 3) / 4, 128>>>(fcw, fcb, out);
}